// round 1
// baseline (speedup 1.0000x reference)
#include <cuda_runtime.h>
#include <math.h>

#define FEAT 32
#define NA 64
#define NE 32

// Scratch: transposed grid (a, e, f) so each (a,e) column is a contiguous 128B line.
__device__ float g_grid_t[NA * NE * FEAT];
__device__ float g_ticks_az[NA];
__device__ float g_ticks_el[NE];
__device__ float g_consts[4];  // inv_so_az, inv_so_el, omega_az_f, omega_el_f

__global__ void prep_kernel(const float* __restrict__ grid) {
    int idx = blockIdx.x * blockDim.x + threadIdx.x;
    if (idx == 0) {
        double oaz = 2.0 * M_PI / (double)NA;          // azimuth tick spacing
        double oel = M_PI / (double)(NE + 1);          // elevation tick spacing
        g_consts[0] = (float)(1.0 / sin(oaz));
        g_consts[1] = (float)(1.0 / sin(oel));
        g_consts[2] = (float)oaz;
        g_consts[3] = (float)oel;
    }
    // Match numpy linspace: arange(i)*step + start in double, then cast f32.
    if (idx < NA)
        g_ticks_az[idx] = (float)((double)idx * (2.0 * M_PI / (double)NA) - M_PI);
    if (idx < NE)
        g_ticks_el[idx] = (float)((double)(idx + 1) * (M_PI / (double)(NE + 1)) - M_PI / 2.0);
    if (idx < FEAT * NA * NE) {
        int f = idx >> 11;          // / (NA*NE)
        int a = (idx >> 5) & 63;    // / NE % NA
        int e = idx & 31;           // % NE
        g_grid_t[(((a << 5) + e) << 5) + f] = grid[idx];
    }
}

__global__ void __launch_bounds__(256)
interp_kernel(const float* __restrict__ pts,
              const float* __restrict__ poles,
              float* __restrict__ out, int n) {
    __shared__ float s_ta[NA];
    __shared__ float s_te[NE];
    __shared__ float s_pole[2 * FEAT];
    __shared__ float s_c[4];

    int t = threadIdx.x;
    if (t < NA) s_ta[t] = g_ticks_az[t];
    if (t < NE) s_te[t] = g_ticks_el[t];
    if (t < 2 * FEAT) s_pole[t] = poles[t];   // layout (F,2): f*2 + pole
    if (t < 4) s_c[t] = g_consts[t];
    __syncthreads();

    int i = blockIdx.x * blockDim.x + t;
    if (i >= n) return;

    float az = pts[i];
    float el = pts[n + i];

    const float inv_so_az = s_c[0];
    const float inv_so_el = s_c[1];
    const float omega_az  = s_c[2];
    const float omega_el  = s_c[3];

    // --- azimuth searchsorted(side='left'): count of ticks strictly < az ---
    int r = (int)((az + 3.14159274101257324f) / omega_az);
    r = min(max(r, 0), NA);
    while (r < NA && s_ta[r] < az) ++r;
    while (r > 0 && s_ta[r - 1] >= az) --r;
    int ar = (r >= NA) ? 0 : r;          // wrap
    int al = (r - 1 < 0) ? (NA - 1) : (r - 1);
    float theta_a = az - s_ta[al];
    float w1a = sinf(omega_az - theta_a) * inv_so_az;
    float w2a = sinf(theta_a) * inv_so_az;

    // --- elevation searchsorted ---
    int q = (int)((el + 1.57079637050628662f) / omega_el);
    q = min(max(q, 0), NE);
    while (q < NE && s_te[q] < el) ++q;
    while (q > 0 && s_te[q - 1] >= el) --q;
    bool south = (q == 0);
    bool north = (q == NE);
    int eil = min(max(q - 1, 0), NE - 1);
    int eir = min(q, NE - 1);
    float base = south ? -1.57079632679489662f : s_te[eil];
    float theta_e = el - base;
    float w1e = sinf(omega_el - theta_e) * inv_so_el;
    float w2e = sinf(theta_e) * inv_so_el;

    const float4* cbl = (const float4*)(g_grid_t + ((((al << 5) + eil)) << 5));
    const float4* cbr = (const float4*)(g_grid_t + ((((ar << 5) + eil)) << 5));
    const float4* ctl = (const float4*)(g_grid_t + ((((al << 5) + eir)) << 5));
    const float4* ctr = (const float4*)(g_grid_t + ((((ar << 5) + eir)) << 5));

#pragma unroll
    for (int f4 = 0; f4 < FEAT / 4; ++f4) {
        float4 bl = cbl[f4];
        float4 br = cbr[f4];
        float4 tl = ctl[f4];
        float4 tr = ctr[f4];
        int f = f4 << 2;

        float fb, ft, f1, f2;

        fb = w1a * bl.x + w2a * br.x;
        ft = w1a * tl.x + w2a * tr.x;
        f1 = south ? s_pole[2 * (f + 0) + 0] : fb;
        f2 = north ? s_pole[2 * (f + 0) + 1] : ft;
        out[(f + 0) * n + i] = w1e * f1 + w2e * f2;

        fb = w1a * bl.y + w2a * br.y;
        ft = w1a * tl.y + w2a * tr.y;
        f1 = south ? s_pole[2 * (f + 1) + 0] : fb;
        f2 = north ? s_pole[2 * (f + 1) + 1] : ft;
        out[(f + 1) * n + i] = w1e * f1 + w2e * f2;

        fb = w1a * bl.z + w2a * br.z;
        ft = w1a * tl.z + w2a * tr.z;
        f1 = south ? s_pole[2 * (f + 2) + 0] : fb;
        f2 = north ? s_pole[2 * (f + 2) + 1] : ft;
        out[(f + 2) * n + i] = w1e * f1 + w2e * f2;

        fb = w1a * bl.w + w2a * br.w;
        ft = w1a * tl.w + w2a * tr.w;
        f1 = south ? s_pole[2 * (f + 3) + 0] : fb;
        f2 = north ? s_pole[2 * (f + 3) + 1] : ft;
        out[(f + 3) * n + i] = w1e * f1 + w2e * f2;
    }
}

extern "C" void kernel_launch(void* const* d_in, const int* in_sizes, int n_in,
                              void* d_out, int out_size) {
    const float* pts   = (const float*)d_in[0];  // (2, N)
    const float* grid  = (const float*)d_in[1];  // (32, 64, 32)
    const float* poles = (const float*)d_in[2];  // (32, 2)
    float* out = (float*)d_out;                  // (32, N)
    int n = in_sizes[0] / 2;

    prep_kernel<<<(FEAT * NA * NE + 255) / 256, 256>>>(grid);
    interp_kernel<<<(n + 255) / 256, 256>>>(pts, poles, out, n);
}

// round 2
// speedup vs baseline: 1.8964x; 1.8964x over previous
#include <cuda_runtime.h>
#include <math.h>

#define FEAT 32
#define NA 64
#define NE 32
#define WARPS 8
#define BLK 256

// Transposed grid (a, e, f): each (a,e) column = 32 floats = one 128B line.
__device__ float g_grid_t[NA * NE * FEAT];
__device__ float g_ticks_az[NA];
__device__ float g_ticks_el[NE];
__device__ float g_consts[4];  // inv_so_az, inv_so_el, omega_az, omega_el

__global__ void prep_kernel(const float* __restrict__ grid) {
    int idx = blockIdx.x * blockDim.x + threadIdx.x;
    if (idx == 0) {
        double oaz = 2.0 * M_PI / (double)NA;
        double oel = M_PI / (double)(NE + 1);
        g_consts[0] = (float)(1.0 / sin(oaz));
        g_consts[1] = (float)(1.0 / sin(oel));
        g_consts[2] = (float)oaz;
        g_consts[3] = (float)oel;
    }
    if (idx < NA)
        g_ticks_az[idx] = (float)((double)idx * (2.0 * M_PI / (double)NA) - M_PI);
    if (idx < NE)
        g_ticks_el[idx] = (float)((double)(idx + 1) * (M_PI / (double)(NE + 1)) - M_PI / 2.0);
    if (idx < FEAT * NA * NE) {
        int f = idx >> 11;
        int a = (idx >> 5) & 63;
        int e = idx & 31;
        g_grid_t[(((a << 5) + e) << 5) + f] = grid[idx];
    }
}

__global__ void __launch_bounds__(BLK)
interp_kernel(const float* __restrict__ pts,
              const float* __restrict__ poles,
              float* __restrict__ out, int n) {
    __shared__ float s_ta[NA];
    __shared__ float s_te[NE];
    __shared__ float s_pole[2][FEAT];
    __shared__ float s_c[4];
    __shared__ int   s_off[WARPS][32][4];
    __shared__ float s_w[WARPS][32][4];
    __shared__ int   s_flag[WARPS][32];
    __shared__ float s_tile[WARPS][32][33];   // [point][feat], padded

    const int t    = threadIdx.x;
    const int warp = t >> 5;
    const int lane = t & 31;

    if (t < NA) s_ta[t] = g_ticks_az[t];
    if (t < NE) s_te[t] = g_ticks_el[t];
    if (t < 2 * FEAT) s_pole[t & 1][t >> 1] = poles[t];  // poles layout (F,2)
    if (t < 4) s_c[t] = g_consts[t];
    __syncthreads();

    const int base = blockIdx.x * BLK + warp * 32;

    // ---------- Phase 1: per-lane point -> indices/weights into smem ----------
    {
        int ip = base + lane;
        int ic = min(ip, n - 1);          // clamp tail; stores guarded later
        float az = pts[ic];
        float el = pts[n + ic];

        const float inv_so_az = s_c[0];
        const float inv_so_el = s_c[1];
        const float omega_az  = s_c[2];
        const float omega_el  = s_c[3];

        // azimuth searchsorted(side='left')
        int r = (int)((az + 3.14159274101257324f) / omega_az);
        r = min(max(r, 0), NA);
        while (r < NA && s_ta[r] < az) ++r;
        while (r > 0 && s_ta[r - 1] >= az) --r;
        int ar = (r >= NA) ? 0 : r;
        int al = (r - 1 < 0) ? (NA - 1) : (r - 1);
        float theta_a = az - s_ta[al];
        float w1a = sinf(omega_az - theta_a) * inv_so_az;
        float w2a = sinf(theta_a) * inv_so_az;

        // elevation searchsorted
        int q = (int)((el + 1.57079637050628662f) / omega_el);
        q = min(max(q, 0), NE);
        while (q < NE && s_te[q] < el) ++q;
        while (q > 0 && s_te[q - 1] >= el) --q;
        bool south = (q == 0);
        bool north = (q == NE);
        int eil = min(max(q - 1, 0), NE - 1);
        int eir = min(q, NE - 1);
        float bse = south ? -1.57079632679489662f : s_te[eil];
        float theta_e = el - bse;
        float w1e = sinf(omega_el - theta_e) * inv_so_el;
        float w2e = sinf(theta_e) * inv_so_el;

        s_off[warp][lane][0] = ((al << 5) + eil) << 5;
        s_off[warp][lane][1] = ((ar << 5) + eil) << 5;
        s_off[warp][lane][2] = ((al << 5) + eir) << 5;
        s_off[warp][lane][3] = ((ar << 5) + eir) << 5;
        s_w[warp][lane][0] = w1a;
        s_w[warp][lane][1] = w2a;
        s_w[warp][lane][2] = w1e;
        s_w[warp][lane][3] = w2e;
        s_flag[warp][lane] = (south ? 1 : 0) | (north ? 2 : 0);
    }
    __syncwarp();

    // ---------- Phase 2: warp-cooperative gather (lane = feature) ----------
    const float pole_s = s_pole[0][lane];
    const float pole_n = s_pole[1][lane];

#pragma unroll 4
    for (int p = 0; p < 32; ++p) {
        int o0 = s_off[warp][p][0];
        int o1 = s_off[warp][p][1];
        int o2 = s_off[warp][p][2];
        int o3 = s_off[warp][p][3];
        float gbl = g_grid_t[o0 + lane];
        float gbr = g_grid_t[o1 + lane];
        float gtl = g_grid_t[o2 + lane];
        float gtr = g_grid_t[o3 + lane];
        float w1a = s_w[warp][p][0];
        float w2a = s_w[warp][p][1];
        float w1e = s_w[warp][p][2];
        float w2e = s_w[warp][p][3];
        int fl = s_flag[warp][p];

        float fb = w1a * gbl + w2a * gbr;
        float ft = w1a * gtl + w2a * gtr;
        float f1 = (fl & 1) ? pole_s : fb;
        float f2 = (fl & 2) ? pole_n : ft;
        s_tile[warp][p][lane] = w1e * f1 + w2e * f2;
    }
    __syncwarp();

    // ---------- Phase 3: coalesced transpose-out (lane = point) ----------
    int ip = base + lane;
    if (ip < n) {
#pragma unroll
        for (int f = 0; f < FEAT; ++f) {
            out[(size_t)f * n + ip] = s_tile[warp][lane][f];
        }
    }
}

extern "C" void kernel_launch(void* const* d_in, const int* in_sizes, int n_in,
                              void* d_out, int out_size) {
    const float* pts   = (const float*)d_in[0];  // (2, N)
    const float* grid  = (const float*)d_in[1];  // (32, 64, 32)
    const float* poles = (const float*)d_in[2];  // (32, 2)
    float* out = (float*)d_out;                  // (32, N)
    int n = in_sizes[0] / 2;

    prep_kernel<<<(FEAT * NA * NE + 255) / 256, 256>>>(grid);
    interp_kernel<<<(n + BLK - 1) / BLK, BLK>>>(pts, poles, out, n);
}

// round 3
// speedup vs baseline: 1.9429x; 1.0245x over previous
#include <cuda_runtime.h>
#include <math.h>

#define FEAT 32
#define NA 64
#define NE 32
#define WARPS 8
#define BLK 256

// Transposed grid (a, e, f): each (a,e) column = 32 floats = one 128B line.
__device__ float g_grid_t[NA * NE * FEAT];
__device__ float g_ticks_az[NA];
__device__ float g_ticks_el[NE];
__device__ float g_consts[4];  // inv_so_az, inv_so_el, omega_az, omega_el

__global__ void prep_kernel(const float* __restrict__ grid) {
    int idx = blockIdx.x * blockDim.x + threadIdx.x;
    if (idx == 0) {
        double oaz = 2.0 * M_PI / (double)NA;
        double oel = M_PI / (double)(NE + 1);
        g_consts[0] = (float)(1.0 / sin(oaz));
        g_consts[1] = (float)(1.0 / sin(oel));
        g_consts[2] = (float)oaz;
        g_consts[3] = (float)oel;
    }
    if (idx < NA)
        g_ticks_az[idx] = (float)((double)idx * (2.0 * M_PI / (double)NA) - M_PI);
    if (idx < NE)
        g_ticks_el[idx] = (float)((double)(idx + 1) * (M_PI / (double)(NE + 1)) - M_PI / 2.0);
    if (idx < FEAT * NA * NE) {
        int f = idx >> 11;
        int a = (idx >> 5) & 63;
        int e = idx & 31;
        g_grid_t[(((a << 5) + e) << 5) + f] = grid[idx];
    }
}

__global__ void __launch_bounds__(BLK)
interp_kernel(const float* __restrict__ pts,
              const float* __restrict__ poles,
              float* __restrict__ out, int n) {
    __shared__ float  s_ta[NA];
    __shared__ float  s_te[NE];
    __shared__ float  s_pole[2][FEAT];
    __shared__ float  s_c[4];
    __shared__ float4 s_cf[WARPS][32];      // {c_bl, c_br, c_tl, c_tr}
    __shared__ float4 s_pk[WARPS][32];      // {o01(bits), o23(bits), ps, pn}
    __shared__ float  s_tile[WARPS][32][33];// [point][feat], padded

    const int t    = threadIdx.x;
    const int warp = t >> 5;
    const int lane = t & 31;

    if (t < NA) s_ta[t] = g_ticks_az[t];
    if (t < NE) s_te[t] = g_ticks_el[t];
    if (t < 2 * FEAT) s_pole[t & 1][t >> 1] = poles[t];  // poles layout (F,2)
    if (t < 4) s_c[t] = g_consts[t];
    __syncthreads();

    const int base = blockIdx.x * BLK + warp * 32;

    // ---------- Phase 1: per-lane point -> 6 coeffs + 4 packed offsets ----------
    {
        int ip = base + lane;
        int ic = min(ip, n - 1);
        float az = pts[ic];
        float el = pts[n + ic];

        const float inv_so_az = s_c[0];
        const float inv_so_el = s_c[1];
        const float omega_az  = s_c[2];
        const float omega_el  = s_c[3];

        // azimuth searchsorted(side='left')
        int r = (int)((az + 3.14159274101257324f) / omega_az);
        r = min(max(r, 0), NA);
        while (r < NA && s_ta[r] < az) ++r;
        while (r > 0 && s_ta[r - 1] >= az) --r;
        int ar = (r >= NA) ? 0 : r;
        int al = (r - 1 < 0) ? (NA - 1) : (r - 1);
        float theta_a = az - s_ta[al];
        float w1a = sinf(omega_az - theta_a) * inv_so_az;
        float w2a = sinf(theta_a) * inv_so_az;

        // elevation searchsorted
        int q = (int)((el + 1.57079637050628662f) / omega_el);
        q = min(max(q, 0), NE);
        while (q < NE && s_te[q] < el) ++q;
        while (q > 0 && s_te[q - 1] >= el) --q;
        bool south = (q == 0);
        bool north = (q == NE);
        int eil = min(max(q - 1, 0), NE - 1);
        int eir = min(q, NE - 1);
        float bse = south ? -1.57079632679489662f : s_te[eil];
        float theta_e = el - bse;
        float w1e = sinf(omega_el - theta_e) * inv_so_el;
        float w2e = sinf(theta_e) * inv_so_el;

        // fold pole handling into coefficients
        float c_bl = south ? 0.0f : w1e * w1a;
        float c_br = south ? 0.0f : w1e * w2a;
        float c_tl = north ? 0.0f : w2e * w1a;
        float c_tr = north ? 0.0f : w2e * w2a;
        float ps   = south ? w1e : 0.0f;
        float pn   = north ? w2e : 0.0f;

        unsigned o0 = (unsigned)(((al << 5) + eil) << 5);
        unsigned o1 = (unsigned)(((ar << 5) + eil) << 5);
        unsigned o2 = (unsigned)(((al << 5) + eir) << 5);
        unsigned o3 = (unsigned)(((ar << 5) + eir) << 5);

        s_cf[warp][lane] = make_float4(c_bl, c_br, c_tl, c_tr);
        s_pk[warp][lane] = make_float4(__uint_as_float(o0 | (o1 << 16)),
                                       __uint_as_float(o2 | (o3 << 16)),
                                       ps, pn);
    }
    __syncwarp();

    // ---------- Phase 2: warp-cooperative gather (lane = feature) ----------
    const float pole_s = s_pole[0][lane];
    const float pole_n = s_pole[1][lane];
    const float* __restrict__ g = g_grid_t;

#pragma unroll 4
    for (int p = 0; p < 32; ++p) {
        float4 pk = s_pk[warp][p];
        float4 cf = s_cf[warp][p];
        unsigned o01 = __float_as_uint(pk.x);
        unsigned o23 = __float_as_uint(pk.y);
        float gbl = g[(o01 & 0xFFFFu) + lane];
        float gbr = g[(o01 >> 16)    + lane];
        float gtl = g[(o23 & 0xFFFFu) + lane];
        float gtr = g[(o23 >> 16)    + lane];
        float res = pk.z * pole_s;
        res = fmaf(pk.w, pole_n, res);
        res = fmaf(cf.x, gbl, res);
        res = fmaf(cf.y, gbr, res);
        res = fmaf(cf.z, gtl, res);
        res = fmaf(cf.w, gtr, res);
        s_tile[warp][p][lane] = res;
    }
    __syncwarp();

    // ---------- Phase 3: coalesced transpose-out ----------
    if (((n & 3) == 0) && (base + 32 <= n)) {
        // vector path: 8 x STG.128 per warp
#pragma unroll
        for (int j = 0; j < 8; ++j) {
            int f  = j * 4 + (lane >> 3);
            int p0 = (lane & 7) * 4;
            float4 v = make_float4(s_tile[warp][p0 + 0][f],
                                   s_tile[warp][p0 + 1][f],
                                   s_tile[warp][p0 + 2][f],
                                   s_tile[warp][p0 + 3][f]);
            *(float4*)(out + (size_t)f * n + base + p0) = v;
        }
    } else {
        int ip = base + lane;
        if (ip < n) {
#pragma unroll
            for (int f = 0; f < FEAT; ++f)
                out[(size_t)f * n + ip] = s_tile[warp][lane][f];
        }
    }
}

extern "C" void kernel_launch(void* const* d_in, const int* in_sizes, int n_in,
                              void* d_out, int out_size) {
    const float* pts   = (const float*)d_in[0];  // (2, N)
    const float* grid  = (const float*)d_in[1];  // (32, 64, 32)
    const float* poles = (const float*)d_in[2];  // (32, 2)
    float* out = (float*)d_out;                  // (32, N)
    int n = in_sizes[0] / 2;

    prep_kernel<<<(FEAT * NA * NE + 255) / 256, 256>>>(grid);
    interp_kernel<<<(n + BLK - 1) / BLK, BLK>>>(pts, poles, out, n);
}